// round 5
// baseline (speedup 1.0000x reference)
#include <cuda_runtime.h>
#include <cuda_bf16.h>
#include <stdint.h>

// ---------------- problem constants ----------------
#define BATCH 8
#define NTOK 4096
#define DIM 768
#define SIM_THRESH 0.2f
#define COS_EPS 1e-8f

// int8 quantization: q = round(v * 127/0.3), sim ~= acc * (0.3/127)^2
#define QSCALE (127.0f / 0.3f)
#define ITHRESH 30000   // acc > 30000  <=> sim > ~0.167  (filter; exact rescore follows)

// ---------------- capacities ----------------
#define GCAP 65536
#define CCAP 32768
#define DCAP 1024
#define RCAP 512

// ---------------- detector tiling ----------------
#define BMD 128
#define BND 256
#define BKB 64                 // BYTES of K per chunk per row
#define KITER (DIM / BKB)      // 12

// ---------------- device scratch ----------------
__device__ int8_t g_q[(size_t)BATCH * NTOK * DIM];            // quantized normalized rows (~25MB)
__device__ float g_inv[BATCH * NTOK];                         // 1/norm per row
__device__ float g_WT[3][DIM * DIM];                          // W^T
// candidates (int filter)
__device__ int g_cd[CCAP];
__device__ int g_ci[CCAP];
__device__ int g_cj[CCAP];
__device__ int g_cc;
// accepted pairs (exact fp32 sim > 0.2), both directions
__device__ int   g_pd[GCAP];
__device__ int   g_pi[GCAP];
__device__ int   g_pj[GCAP];
__device__ float g_ps[GCAP];
__device__ int   g_pc;
// per-doc sparse metadata
__device__ int   g_np[BATCH], g_ns[BATCH];
__device__ int   g_dpj[BATCH][DCAP];
__device__ float g_dps[BATCH][DCAP];
__device__ int   g_djx[BATCH][DCAP];
__device__ int   g_rows[BATCH][RCAP];
__device__ int   g_rowptr[BATCH][RCAP + 1];
// activations for special rows
__device__ float g_h[2][BATCH][RCAP][DIM];

// ---------------- helpers ----------------
__device__ __forceinline__ uint32_t smem_u32(const void* p) {
    uint32_t a;
    asm("{ .reg .u64 t; cvta.to.shared.u64 t, %1; cvt.u32.u64 %0, t; }" : "=r"(a) : "l"(p));
    return a;
}
#define SW64(off) ((off) ^ (((off) >> 3) & 0x30))

__device__ __forceinline__ void cp16(uint32_t dst, const void* src) {
    asm volatile("cp.async.cg.shared.global [%0], [%1], 16;" :: "r"(dst), "l"(src) : "memory");
}
#define CP_COMMIT() asm volatile("cp.async.commit_group;" ::: "memory")
#define CP_WAIT0()  asm volatile("cp.async.wait_group 0;" ::: "memory")

__device__ __forceinline__ void ldm_x4(uint32_t& r0, uint32_t& r1, uint32_t& r2, uint32_t& r3, uint32_t addr) {
    asm volatile("ldmatrix.sync.aligned.m8n8.x4.shared.b16 {%0,%1,%2,%3}, [%4];"
                 : "=r"(r0), "=r"(r1), "=r"(r2), "=r"(r3) : "r"(addr));
}
__device__ __forceinline__ void imma16832(int* c, const uint32_t* a, const uint32_t* b) {
    asm volatile("mma.sync.aligned.m16n8k32.row.col.s32.s8.s8.s32 "
                 "{%0,%1,%2,%3}, {%4,%5,%6,%7}, {%8,%9}, {%0,%1,%2,%3};"
                 : "+r"(c[0]), "+r"(c[1]), "+r"(c[2]), "+r"(c[3])
                 : "r"(a[0]), "r"(a[1]), "r"(a[2]), "r"(a[3]), "r"(b[0]), "r"(b[1]));
}

// ---------------- kernel 0: transpose weights ----------------
__global__ void ktrans(const float* __restrict__ W1, const float* __restrict__ W2,
                       const float* __restrict__ W3) {
    int idx = blockIdx.x * blockDim.x + threadIdx.x;
    if (idx >= 3 * DIM * DIM) return;
    int m = idx / (DIM * DIM);
    int r = idx % (DIM * DIM);
    int o = r % DIM, k = r / DIM;
    const float* W = (m == 0) ? W1 : (m == 1 ? W2 : W3);
    g_WT[m][r] = W[(size_t)o * DIM + k];
}

// ---------------- kernel 1: normalize -> int8, inv norms, reset counters ----------------
__global__ void knorm(const float* __restrict__ emb) {
    int row = blockIdx.x;
    if (row == 0 && threadIdx.x == 0) { g_pc = 0; g_cc = 0; }
    const float* e = emb + (size_t)row * DIM;
    float ss = 0.f;
    for (int k = threadIdx.x; k < DIM; k += 256) { float v = e[k]; ss += v * v; }
    for (int o = 16; o > 0; o >>= 1) ss += __shfl_xor_sync(0xffffffffu, ss, o);
    __shared__ float red[8];
    int w = threadIdx.x >> 5, lane = threadIdx.x & 31;
    if (lane == 0) red[w] = ss;
    __syncthreads();
    if (w == 0) {
        float tot = (lane < 8) ? red[lane] : 0.f;
        for (int o = 4; o > 0; o >>= 1) tot += __shfl_xor_sync(0xffffffffu, tot, o);
        if (lane == 0) red[0] = tot;
    }
    __syncthreads();
    float inv = 1.0f / fmaxf(sqrtf(red[0]), COS_EPS);
    if (threadIdx.x == 0) g_inv[row] = inv;
    float s = inv * QSCALE;
    int k0 = threadIdx.x * 4;
    if (k0 < DIM) {
        float4 v = *(const float4*)(e + k0);
        char4 q;
        q.x = (char)__float2int_rn(fmaxf(fminf(v.x * s, 127.f), -127.f));
        q.y = (char)__float2int_rn(fmaxf(fminf(v.y * s, 127.f), -127.f));
        q.z = (char)__float2int_rn(fmaxf(fminf(v.z * s, 127.f), -127.f));
        q.w = (char)__float2int_rn(fmaxf(fminf(v.w * s, 127.f), -127.f));
        *(char4*)(g_q + (size_t)row * DIM + k0) = q;
    }
}

// ---------------- kernel 2: int8 mma.sync similarity detector (128x256 CTA, 64x64 warp) ----------------
__global__ void __launch_bounds__(256, 1) kdet() {
    int bx = blockIdx.x, by = blockIdx.y, d = blockIdx.z;
    if (bx < 2 * by) return;   // tile has no i>j pairs

    __shared__ __align__(128) unsigned char As[2][BMD * BKB];   // 8KB per stage
    __shared__ __align__(128) unsigned char Bs[2][BND * BKB];   // 16KB per stage

    int t = threadIdx.x, wid = t >> 5, lane = t & 31;
    int wm = wid & 1;        // 2 warps along M (64 rows each)
    int wn = wid >> 1;       // 4 warps along N (64 cols each)

    const int8_t* Ag = g_q + ((size_t)d * NTOK + (size_t)bx * BMD) * DIM;
    const int8_t* Bg = g_q + ((size_t)d * NTOK + (size_t)by * BND) * DIM;

    uint32_t AsA[2] = { smem_u32(As[0]), smem_u32(As[1]) };
    uint32_t BsA[2] = { smem_u32(Bs[0]), smem_u32(Bs[1]) };

    // A: 128 rows x 4 segs = 512 segs -> 2 per thread; B: 256 rows x 4 segs = 1024 -> 4 per thread
    int rowa[2], sega[2]; uint32_t soffa[2];
#pragma unroll
    for (int u = 0; u < 2; u++) {
        int q = t + 256 * u;
        rowa[u] = q >> 2; sega[u] = q & 3;
        soffa[u] = SW64((uint32_t)(rowa[u] * 64 + sega[u] * 16));
    }
    int rowb[4], segb[4]; uint32_t soffb[4];
#pragma unroll
    for (int u = 0; u < 4; u++) {
        int q = t + 256 * u;
        rowb[u] = q >> 2; segb[u] = q & 3;
        soffb[u] = SW64((uint32_t)(rowb[u] * 64 + segb[u] * 16));
    }

    // prologue: chunk 0 -> stage 0
#pragma unroll
    for (int u = 0; u < 2; u++)
        cp16(AsA[0] + soffa[u], Ag + (size_t)rowa[u] * DIM + sega[u] * 16);
#pragma unroll
    for (int u = 0; u < 4; u++)
        cp16(BsA[0] + soffb[u], Bg + (size_t)rowb[u] * DIM + segb[u] * 16);
    CP_COMMIT();

    int acc[4][8][4];
#pragma unroll
    for (int mi = 0; mi < 4; mi++)
#pragma unroll
        for (int ni = 0; ni < 8; ni++)
#pragma unroll
            for (int e = 0; e < 4; e++) acc[mi][ni][e] = 0;

    for (int kb = 0; kb < KITER; kb++) {
        int cur = kb & 1;
        CP_WAIT0();            // chunk kb landed
        __syncthreads();       // visible to all; everyone done reading stage cur^1
        if (kb + 1 < KITER) {  // prefetch chunk kb+1 into the other stage (overlaps compute)
            int nxt = cur ^ 1;
            int k0 = (kb + 1) * BKB;
#pragma unroll
            for (int u = 0; u < 2; u++)
                cp16(AsA[nxt] + soffa[u], Ag + (size_t)rowa[u] * DIM + k0 + sega[u] * 16);
#pragma unroll
            for (int u = 0; u < 4; u++)
                cp16(BsA[nxt] + soffb[u], Bg + (size_t)rowb[u] * DIM + k0 + segb[u] * 16);
            CP_COMMIT();
        }

#pragma unroll
        for (int ks = 0; ks < 2; ks++) {
            uint32_t af[4][4];
#pragma unroll
            for (int mi = 0; mi < 4; mi++) {
                int row = wm * 64 + mi * 16 + (lane & 15);
                int bcol = ks * 32 + ((lane >> 4) << 4);
                uint32_t addr = AsA[cur] + SW64((uint32_t)(row * 64 + bcol));
                ldm_x4(af[mi][0], af[mi][1], af[mi][2], af[mi][3], addr);
            }
            uint32_t bfr[8][2];
#pragma unroll
            for (int pair = 0; pair < 4; pair++) {
                int g = lane >> 3;
                int row = wn * 64 + pair * 16 + ((g >> 1) << 3) + (lane & 7);
                int bcol = ks * 32 + ((g & 1) << 4);
                uint32_t addr = BsA[cur] + SW64((uint32_t)(row * 64 + bcol));
                uint32_t r0, r1, r2, r3;
                ldm_x4(r0, r1, r2, r3, addr);
                bfr[pair * 2][0] = r0; bfr[pair * 2][1] = r1;
                bfr[pair * 2 + 1][0] = r2; bfr[pair * 2 + 1][1] = r3;
            }
#pragma unroll
            for (int mi = 0; mi < 4; mi++)
#pragma unroll
                for (int ni = 0; ni < 8; ni++)
                    imma16832(acc[mi][ni], af[mi], bfr[ni]);
        }
    }

    // epilogue: integer threshold from accumulators
    int i_base = bx * BMD + wm * 64;
    int j_base = by * BND + wn * 64;
#pragma unroll
    for (int mi = 0; mi < 4; mi++) {
#pragma unroll
        for (int ni = 0; ni < 8; ni++) {
#pragma unroll
            for (int e = 0; e < 4; e++) {
                if (acc[mi][ni][e] > ITHRESH) {
                    int i = i_base + mi * 16 + (lane >> 2) + ((e >> 1) << 3);
                    int j = j_base + ni * 8 + ((lane & 3) << 1) + (e & 1);
                    if (i > j) {
                        int idx = atomicAdd(&g_cc, 1);
                        if (idx < CCAP) { g_cd[idx] = d; g_ci[idx] = i; g_cj[idx] = j; }
                    }
                }
            }
        }
    }
}

// ---------------- kernel 3: exact fp32 rescore of candidates ----------------
__global__ void krescore(const float* __restrict__ emb) {
    int C = g_cc; if (C > CCAP) C = CCAP;
    int nwarps = (gridDim.x * blockDim.x) >> 5;
    int w = (blockIdx.x * blockDim.x + threadIdx.x) >> 5;
    int lane = threadIdx.x & 31;
    for (int c = w; c < C; c += nwarps) {
        int d = g_cd[c], i = g_ci[c], j = g_cj[c];
        const float* ei = emb + ((size_t)d * NTOK + i) * DIM;
        const float* ej = emb + ((size_t)d * NTOK + j) * DIM;
        float acc = 0.f;
        for (int k = lane; k < DIM; k += 32) acc += ei[k] * ej[k];
        for (int o = 16; o > 0; o >>= 1) acc += __shfl_xor_sync(0xffffffffu, acc, o);
        if (lane == 0) {
            float s = acc * g_inv[d * NTOK + i] * g_inv[d * NTOK + j];
            if (s > SIM_THRESH) {
                int idx = atomicAdd(&g_pc, 2);
                if (idx + 1 < GCAP) {
                    g_pd[idx] = d; g_pi[idx] = i; g_pj[idx] = j; g_ps[idx] = s;
                    g_pd[idx + 1] = d; g_pi[idx + 1] = j; g_pj[idx + 1] = i; g_ps[idx + 1] = s;
                }
            }
        }
    }
}

// ---------------- kernel 4: per-doc pair metadata (deterministic sort) ----------------
__global__ void kprep() {
    int d = blockIdx.x;
    if (threadIdx.x != 0) return;
    int P = g_pc; if (P > GCAP) P = GCAP;
    int spi[256];
    int np = 0;
    for (int p = 0; p < P && np < 256; p++)
        if (g_pd[p] == d) spi[np++] = p;
    for (int a = 1; a < np; a++) {
        int pa = spi[a];
        long key = (long)g_pi[pa] * NTOK + g_pj[pa];
        int b = a - 1;
        while (b >= 0 && (long)g_pi[spi[b]] * NTOK + g_pj[spi[b]] > key) { spi[b + 1] = spi[b]; b--; }
        spi[b + 1] = pa;
    }
    int ns = 0;
    for (int p = 0; p < np; p++) {
        int i = g_pi[spi[p]];
        if (ns == 0 || g_rows[d][ns - 1] != i) {
            if (ns < RCAP) { g_rows[d][ns] = i; g_rowptr[d][ns] = p; ns++; }
        }
        g_dpj[d][p] = g_pj[spi[p]];
        g_dps[d][p] = g_ps[spi[p]];
    }
    g_rowptr[d][ns] = np;
    for (int p = 0; p < np; p++) {
        int lo = 0, hi = ns - 1, f = -1, v = g_dpj[d][p];
        while (lo <= hi) {
            int mid = (lo + hi) >> 1; int rv = g_rows[d][mid];
            if (rv == v) { f = mid; break; }
            if (rv < v) lo = mid + 1; else hi = mid - 1;
        }
        g_djx[d][p] = f;
    }
    g_np[d] = np; g_ns[d] = ns;
}

// ---------------- kernel 5: one GNN layer on special rows ----------------
__global__ void klayer(int l, const float* __restrict__ emb,
                       const float* __restrict__ bprev, const float* __restrict__ bcur) {
    int d = blockIdx.y, cx = blockIdx.x, t = threadIdx.x;  // 128 threads
    int ns = g_ns[d];
    if (ns == 0) return;
    __shared__ float y[DIM];
    const float* WT = g_WT[l];
    int rd = (l + 1) & 1;
    int wr = l & 1;
    for (int ii = 0; ii < ns; ii++) {
        for (int k = t; k < DIM; k += 128) {
            float a = 0.f;
            int p0 = g_rowptr[d][ii], p1 = g_rowptr[d][ii + 1];
            for (int p = p0; p < p1; p++) {
                float v;
                if (l == 0) {
                    v = emb[((size_t)d * NTOK + g_dpj[d][p]) * DIM + k];
                } else {
                    int jx = g_djx[d][p];
                    v = (jx >= 0) ? g_h[rd][d][jx][k] : fmaxf(bprev[k], 0.f);
                }
                a += g_dps[d][p] * v;
            }
            y[k] = a;
        }
        __syncthreads();
        int c = cx * 128 + t;
        float acc = bcur[c];
#pragma unroll 16
        for (int k = 0; k < DIM; k++) acc = fmaf(y[k], WT[(size_t)k * DIM + c], acc);
        g_h[wr][d][ii][c] = fmaxf(acc, 0.f);
        __syncthreads();
    }
}

// ---------------- kernel 6: output mean ----------------
__global__ void kout(const float* __restrict__ b3, float* __restrict__ out) {
    int d = blockIdx.x, t = threadIdx.x;  // 768 threads
    float c3 = fmaxf(b3[t], 0.f);
    float acc = c3;
    int ns = g_ns[d];
    for (int ii = 0; ii < ns; ii++)
        acc += (g_h[0][d][ii][t] - c3) * (1.0f / (float)NTOK);
    out[(size_t)d * DIM + t] = acc;
}

// ---------------- launch ----------------
extern "C" void kernel_launch(void* const* d_in, const int* in_sizes, int n_in,
                              void* d_out, int out_size) {
    const float* emb = (const float*)d_in[0];
    const float* W1  = (const float*)d_in[1];
    const float* b1  = (const float*)d_in[2];
    const float* W2  = (const float*)d_in[3];
    const float* b2  = (const float*)d_in[4];
    const float* W3  = (const float*)d_in[5];
    const float* b3  = (const float*)d_in[6];
    float* out = (float*)d_out;

    ktrans<<<(3 * DIM * DIM + 255) / 256, 256>>>(W1, W2, W3);
    knorm<<<BATCH * NTOK, 256>>>(emb);
    dim3 g(NTOK / BMD, NTOK / BND, BATCH);   // 32 x 16 x 8, keep-mask bx >= 2*by
    kdet<<<g, 256>>>();
    krescore<<<32, 128>>>(emb);
    kprep<<<BATCH, 32>>>();
    klayer<<<dim3(6, BATCH), 128>>>(0, emb, b1, b1);
    klayer<<<dim3(6, BATCH), 128>>>(1, emb, b1, b2);
    klayer<<<dim3(6, BATCH), 128>>>(2, emb, b2, b3);
    kout<<<BATCH, DIM>>>(b3, out);
}

// round 6
// speedup vs baseline: 1.3156x; 1.3156x over previous
#include <cuda_runtime.h>
#include <cuda_bf16.h>
#include <stdint.h>

// ---------------- problem constants ----------------
#define BATCH 8
#define NTOK 4096
#define DIM 768
#define SIM_THRESH 0.2f
#define COS_EPS 1e-8f

// int8 quantization: q = round(v * 127/0.3), sim ~= acc * (0.3/127)^2
#define QSCALE (127.0f / 0.3f)
#define ITHRESH 30000   // acc > 30000  <=> sim > ~0.167  (filter; exact rescore follows)

// ---------------- capacities ----------------
#define GCAP 65536
#define CCAP 32768
#define DCAP 1024
#define RCAP 512

// ---------------- detector tiling (proven R4 config) ----------------
#define BM 128
#define BN 128
#define BKB 64                 // BYTES of K per chunk per row
#define KITER (DIM / BKB)      // 12
#define STAGES 3

// ---------------- device scratch ----------------
__device__ int8_t g_q[(size_t)BATCH * NTOK * DIM];            // quantized normalized rows (~25MB)
__device__ float g_inv[BATCH * NTOK];                         // 1/norm per row
__device__ float g_WT[3][DIM * DIM];                          // W^T
// candidates (int filter)
__device__ int g_cd[CCAP];
__device__ int g_ci[CCAP];
__device__ int g_cj[CCAP];
__device__ int g_cc;
// accepted pairs (exact fp32 sim > 0.2), both directions
__device__ int   g_pd[GCAP];
__device__ int   g_pi[GCAP];
__device__ int   g_pj[GCAP];
__device__ float g_ps[GCAP];
__device__ int   g_pc;
// per-doc sparse metadata
__device__ int   g_np[BATCH], g_ns[BATCH];
__device__ int   g_dpj[BATCH][DCAP];
__device__ float g_dps[BATCH][DCAP];
__device__ int   g_djx[BATCH][DCAP];
__device__ int   g_rows[BATCH][RCAP];
__device__ int   g_rowptr[BATCH][RCAP + 1];
// activations for special rows
__device__ float g_h[2][BATCH][RCAP][DIM];

// ---------------- helpers ----------------
__device__ __forceinline__ uint32_t smem_u32(const void* p) {
    uint32_t a;
    asm("{ .reg .u64 t; cvta.to.shared.u64 t, %1; cvt.u32.u64 %0, t; }" : "=r"(a) : "l"(p));
    return a;
}
#define SW64(off) ((off) ^ (((off) >> 3) & 0x30))

__device__ __forceinline__ void cp16(uint32_t dst, const void* src) {
    asm volatile("cp.async.cg.shared.global [%0], [%1], 16;" :: "r"(dst), "l"(src) : "memory");
}
#define CP_COMMIT() asm volatile("cp.async.commit_group;" ::: "memory")
#define CP_WAIT1()  asm volatile("cp.async.wait_group 1;" ::: "memory")

__device__ __forceinline__ void ldm_x4(uint32_t& r0, uint32_t& r1, uint32_t& r2, uint32_t& r3, uint32_t addr) {
    asm volatile("ldmatrix.sync.aligned.m8n8.x4.shared.b16 {%0,%1,%2,%3}, [%4];"
                 : "=r"(r0), "=r"(r1), "=r"(r2), "=r"(r3) : "r"(addr));
}
__device__ __forceinline__ void imma16832(int* c, const uint32_t* a, const uint32_t* b) {
    asm volatile("mma.sync.aligned.m16n8k32.row.col.s32.s8.s8.s32 "
                 "{%0,%1,%2,%3}, {%4,%5,%6,%7}, {%8,%9}, {%0,%1,%2,%3};"
                 : "+r"(c[0]), "+r"(c[1]), "+r"(c[2]), "+r"(c[3])
                 : "r"(a[0]), "r"(a[1]), "r"(a[2]), "r"(a[3]), "r"(b[0]), "r"(b[1]));
}

// ---------------- kernel 0: smem-tiled transpose (coalesced both sides) ----------------
__global__ void ktrans(const float* __restrict__ W1, const float* __restrict__ W2,
                       const float* __restrict__ W3) {
    __shared__ float s[32][33];
    int m = blockIdx.z;
    const float* W = (m == 0) ? W1 : (m == 1 ? W2 : W3);
    int tx = threadIdx.x, ty = threadIdx.y;           // 32 x 8
    int k0 = blockIdx.x * 32, o0 = blockIdx.y * 32;
    // read W[o][k]: o slow, k fast (coalesced over tx)
#pragma unroll
    for (int j = 0; j < 32; j += 8)
        s[ty + j][tx] = W[(size_t)(o0 + ty + j) * DIM + (k0 + tx)];
    __syncthreads();
    // write WT[k][o] = W[o][k]: coalesced over tx in o
#pragma unroll
    for (int j = 0; j < 32; j += 8)
        g_WT[m][(size_t)(k0 + ty + j) * DIM + (o0 + tx)] = s[tx][ty + j];
}

// ---------------- kernel 1: normalize -> int8 (one warp per row) ----------------
__global__ void knorm(const float* __restrict__ emb) {
    int gw = (blockIdx.x * blockDim.x + threadIdx.x) >> 5;   // global warp = row
    int lane = threadIdx.x & 31;
    if (gw >= BATCH * NTOK) return;
    if (gw == 0 && lane == 0) { g_pc = 0; g_cc = 0; }
    const float4* e4 = (const float4*)(emb + (size_t)gw * DIM);
    float4 v[6];
    float ss = 0.f;
#pragma unroll
    for (int u = 0; u < 6; u++) {
        v[u] = e4[u * 32 + lane];
        ss += v[u].x * v[u].x + v[u].y * v[u].y + v[u].z * v[u].z + v[u].w * v[u].w;
    }
#pragma unroll
    for (int o = 16; o > 0; o >>= 1) ss += __shfl_xor_sync(0xffffffffu, ss, o);
    float inv = 1.0f / fmaxf(sqrtf(ss), COS_EPS);
    if (lane == 0) g_inv[gw] = inv;
    float s = inv * QSCALE;
    char4* q4 = (char4*)(g_q + (size_t)gw * DIM);
#pragma unroll
    for (int u = 0; u < 6; u++) {
        char4 q;
        q.x = (char)__float2int_rn(fmaxf(fminf(v[u].x * s, 127.f), -127.f));
        q.y = (char)__float2int_rn(fmaxf(fminf(v[u].y * s, 127.f), -127.f));
        q.z = (char)__float2int_rn(fmaxf(fminf(v[u].z * s, 127.f), -127.f));
        q.w = (char)__float2int_rn(fmaxf(fminf(v[u].w * s, 127.f), -127.f));
        q4[u * 32 + lane] = q;
    }
}

// ---------------- kernel 2: int8 mma.sync similarity detector (R4 proven config) ----------------
__global__ void __launch_bounds__(256, 2) kdet() {
    int lin = blockIdx.x, d = blockIdx.z;
    // triangular decode: lin -> (bx, by), by <= bx
    int bx = (int)((sqrtf(8.f * (float)lin + 1.f) - 1.f) * 0.5f);
    while ((bx + 1) * (bx + 2) / 2 <= lin) bx++;
    while (bx * (bx + 1) / 2 > lin) bx--;
    int by = lin - bx * (bx + 1) / 2;

    __shared__ __align__(128) unsigned char As[STAGES][BM * BKB];   // 8KB per stage
    __shared__ __align__(128) unsigned char Bs[STAGES][BM * BKB];

    int t = threadIdx.x, wid = t >> 5, lane = t & 31;
    int wm = wid & 1;        // 2 warps along M (64 rows each)
    int wn = wid >> 1;       // 4 warps along N (32 cols each)

    const int8_t* Ag = g_q + ((size_t)d * NTOK + (size_t)bx * BM) * DIM;
    const int8_t* Bg = g_q + ((size_t)d * NTOK + (size_t)by * BN) * DIM;

    uint32_t AsA[STAGES], BsA[STAGES];
#pragma unroll
    for (int s = 0; s < STAGES; s++) { AsA[s] = smem_u32(As[s]); BsA[s] = smem_u32(Bs[s]); }

    int rowq[2], segq[2];
    uint32_t soffq[2];
#pragma unroll
    for (int u = 0; u < 2; u++) {
        int q = t + 256 * u;
        rowq[u] = q >> 2; segq[u] = q & 3;
        soffq[u] = SW64((uint32_t)(rowq[u] * 64 + segq[u] * 16));
    }

    // prologue: fill stages 0,1 with chunks 0,1
#pragma unroll
    for (int s = 0; s < STAGES - 1; s++) {
        int k0 = s * BKB;
#pragma unroll
        for (int u = 0; u < 2; u++) {
            cp16(AsA[s] + soffq[u], Ag + (size_t)rowq[u] * DIM + k0 + segq[u] * 16);
            cp16(BsA[s] + soffq[u], Bg + (size_t)rowq[u] * DIM + k0 + segq[u] * 16);
        }
        CP_COMMIT();
    }

    int acc[4][4][4];
#pragma unroll
    for (int mi = 0; mi < 4; mi++)
#pragma unroll
        for (int ni = 0; ni < 4; ni++)
#pragma unroll
            for (int e = 0; e < 4; e++) acc[mi][ni][e] = 0;

    int cur = 0;
    for (int kb = 0; kb < KITER; kb++) {
        CP_WAIT1();
        __syncthreads();
        int nk = kb + STAGES - 1;
        if (nk < KITER) {
            int s = nk % STAGES;
            int k0 = nk * BKB;
#pragma unroll
            for (int u = 0; u < 2; u++) {
                cp16(AsA[s] + soffq[u], Ag + (size_t)rowq[u] * DIM + k0 + segq[u] * 16);
                cp16(BsA[s] + soffq[u], Bg + (size_t)rowq[u] * DIM + k0 + segq[u] * 16);
            }
        }
        CP_COMMIT();

#pragma unroll
        for (int ks = 0; ks < 2; ks++) {
            uint32_t af[4][4];
#pragma unroll
            for (int mi = 0; mi < 4; mi++) {
                int row = wm * 64 + mi * 16 + (lane & 15);
                int bcol = ks * 32 + ((lane >> 4) << 4);
                uint32_t addr = AsA[cur] + SW64((uint32_t)(row * 64 + bcol));
                ldm_x4(af[mi][0], af[mi][1], af[mi][2], af[mi][3], addr);
            }
            uint32_t bfr[4][2];
#pragma unroll
            for (int pair = 0; pair < 2; pair++) {
                int g = lane >> 3;
                int row = wn * 32 + pair * 16 + ((g >> 1) << 3) + (lane & 7);
                int bcol = ks * 32 + ((g & 1) << 4);
                uint32_t addr = BsA[cur] + SW64((uint32_t)(row * 64 + bcol));
                uint32_t r0, r1, r2, r3;
                ldm_x4(r0, r1, r2, r3, addr);
                bfr[pair * 2][0] = r0; bfr[pair * 2][1] = r1;
                bfr[pair * 2 + 1][0] = r2; bfr[pair * 2 + 1][1] = r3;
            }
#pragma unroll
            for (int mi = 0; mi < 4; mi++)
#pragma unroll
                for (int ni = 0; ni < 4; ni++)
                    imma16832(acc[mi][ni], af[mi], bfr[ni]);
        }
        cur = (cur + 1) % STAGES;
    }

    // epilogue: integer threshold from accumulators
    int i_base = bx * BM + wm * 64;
    int j_base = by * BN + wn * 32;
#pragma unroll
    for (int mi = 0; mi < 4; mi++) {
#pragma unroll
        for (int ni = 0; ni < 4; ni++) {
#pragma unroll
            for (int e = 0; e < 4; e++) {
                if (acc[mi][ni][e] > ITHRESH) {
                    int i = i_base + mi * 16 + (lane >> 2) + ((e >> 1) << 3);
                    int j = j_base + ni * 8 + ((lane & 3) << 1) + (e & 1);
                    if (i > j) {
                        int idx = atomicAdd(&g_cc, 1);
                        if (idx < CCAP) { g_cd[idx] = d; g_ci[idx] = i; g_cj[idx] = j; }
                    }
                }
            }
        }
    }
}

// ---------------- kernel 3: exact fp32 rescore of candidates ----------------
__global__ void krescore(const float* __restrict__ emb) {
    int C = g_cc; if (C > CCAP) C = CCAP;
    int nwarps = (gridDim.x * blockDim.x) >> 5;
    int w = (blockIdx.x * blockDim.x + threadIdx.x) >> 5;
    int lane = threadIdx.x & 31;
    for (int c = w; c < C; c += nwarps) {
        int d = g_cd[c], i = g_ci[c], j = g_cj[c];
        const float* ei = emb + ((size_t)d * NTOK + i) * DIM;
        const float* ej = emb + ((size_t)d * NTOK + j) * DIM;
        float acc = 0.f;
        for (int k = lane; k < DIM; k += 32) acc += ei[k] * ej[k];
        for (int o = 16; o > 0; o >>= 1) acc += __shfl_xor_sync(0xffffffffu, acc, o);
        if (lane == 0) {
            float s = acc * g_inv[d * NTOK + i] * g_inv[d * NTOK + j];
            if (s > SIM_THRESH) {
                int idx = atomicAdd(&g_pc, 2);
                if (idx + 1 < GCAP) {
                    g_pd[idx] = d; g_pi[idx] = i; g_pj[idx] = j; g_ps[idx] = s;
                    g_pd[idx + 1] = d; g_pi[idx + 1] = j; g_pj[idx + 1] = i; g_ps[idx + 1] = s;
                }
            }
        }
    }
}

// ---------------- kernel 4: per-doc pair metadata (deterministic sort) ----------------
__global__ void kprep() {
    int d = blockIdx.x;
    if (threadIdx.x != 0) return;
    int P = g_pc; if (P > GCAP) P = GCAP;
    int spi[256];
    int np = 0;
    for (int p = 0; p < P && np < 256; p++)
        if (g_pd[p] == d) spi[np++] = p;
    for (int a = 1; a < np; a++) {
        int pa = spi[a];
        long key = (long)g_pi[pa] * NTOK + g_pj[pa];
        int b = a - 1;
        while (b >= 0 && (long)g_pi[spi[b]] * NTOK + g_pj[spi[b]] > key) { spi[b + 1] = spi[b]; b--; }
        spi[b + 1] = pa;
    }
    int ns = 0;
    for (int p = 0; p < np; p++) {
        int i = g_pi[spi[p]];
        if (ns == 0 || g_rows[d][ns - 1] != i) {
            if (ns < RCAP) { g_rows[d][ns] = i; g_rowptr[d][ns] = p; ns++; }
        }
        g_dpj[d][p] = g_pj[spi[p]];
        g_dps[d][p] = g_ps[spi[p]];
    }
    g_rowptr[d][ns] = np;
    for (int p = 0; p < np; p++) {
        int lo = 0, hi = ns - 1, f = -1, v = g_dpj[d][p];
        while (lo <= hi) {
            int mid = (lo + hi) >> 1; int rv = g_rows[d][mid];
            if (rv == v) { f = mid; break; }
            if (rv < v) lo = mid + 1; else hi = mid - 1;
        }
        g_djx[d][p] = f;
    }
    g_np[d] = np; g_ns[d] = ns;
}

// ---------------- kernel 5: one GNN layer on special rows ----------------
__global__ void klayer(int l, const float* __restrict__ emb,
                       const float* __restrict__ bprev, const float* __restrict__ bcur) {
    int d = blockIdx.y, cx = blockIdx.x, t = threadIdx.x;  // 128 threads
    int ns = g_ns[d];
    if (ns == 0) return;
    __shared__ float y[DIM];
    const float* WT = g_WT[l];
    int rd = (l + 1) & 1;
    int wr = l & 1;
    for (int ii = 0; ii < ns; ii++) {
        for (int k = t; k < DIM; k += 128) {
            float a = 0.f;
            int p0 = g_rowptr[d][ii], p1 = g_rowptr[d][ii + 1];
            for (int p = p0; p < p1; p++) {
                float v;
                if (l == 0) {
                    v = emb[((size_t)d * NTOK + g_dpj[d][p]) * DIM + k];
                } else {
                    int jx = g_djx[d][p];
                    v = (jx >= 0) ? g_h[rd][d][jx][k] : fmaxf(bprev[k], 0.f);
                }
                a += g_dps[d][p] * v;
            }
            y[k] = a;
        }
        __syncthreads();
        int c = cx * 128 + t;
        float acc = bcur[c];
#pragma unroll 16
        for (int k = 0; k < DIM; k++) acc = fmaf(y[k], WT[(size_t)k * DIM + c], acc);
        g_h[wr][d][ii][c] = fmaxf(acc, 0.f);
        __syncthreads();
    }
}

// ---------------- kernel 6: output mean ----------------
__global__ void kout(const float* __restrict__ b3, float* __restrict__ out) {
    int d = blockIdx.x, t = threadIdx.x;  // 768 threads
    float c3 = fmaxf(b3[t], 0.f);
    float acc = c3;
    int ns = g_ns[d];
    for (int ii = 0; ii < ns; ii++)
        acc += (g_h[0][d][ii][t] - c3) * (1.0f / (float)NTOK);
    out[(size_t)d * DIM + t] = acc;
}

// ---------------- launch ----------------
extern "C" void kernel_launch(void* const* d_in, const int* in_sizes, int n_in,
                              void* d_out, int out_size) {
    const float* emb = (const float*)d_in[0];
    const float* W1  = (const float*)d_in[1];
    const float* b1  = (const float*)d_in[2];
    const float* W2  = (const float*)d_in[3];
    const float* b2  = (const float*)d_in[4];
    const float* W3  = (const float*)d_in[5];
    const float* b3  = (const float*)d_in[6];
    float* out = (float*)d_out;

    dim3 tb(32, 8);
    dim3 tg(DIM / 32, DIM / 32, 3);
    ktrans<<<tg, tb>>>(W1, W2, W3);
    knorm<<<(BATCH * NTOK) / 8, 256>>>(emb);   // one warp per row, 8 warps/block
    int nblk = NTOK / BM;                       // 32
    dim3 g(nblk * (nblk + 1) / 2, 1, BATCH);    // 528 x 8
    kdet<<<g, 256>>>();
    krescore<<<32, 128>>>(emb);
    kprep<<<BATCH, 32>>>();
    klayer<<<dim3(6, BATCH), 128>>>(0, emb, b1, b1);
    klayer<<<dim3(6, BATCH), 128>>>(1, emb, b1, b2);
    klayer<<<dim3(6, BATCH), 128>>>(2, emb, b2, b3);
    kout<<<BATCH, DIM>>>(b3, out);
}